// round 9
// baseline (speedup 1.0000x reference)
#include <cuda_runtime.h>
#include <cstdint>

#define ULL unsigned long long

// ---------- packed f32x2 helpers (sm_100+ PTX) ----------
__device__ __forceinline__ void fma2(ULL& d, ULL a, ULL b) {
    asm("fma.rn.f32x2 %0, %1, %2, %0;" : "+l"(d) : "l"(a), "l"(b));
}
__device__ __forceinline__ ULL mul2(ULL a, ULL b) {
    ULL d; asm("mul.rn.f32x2 %0, %1, %2;" : "=l"(d) : "l"(a), "l"(b)); return d;
}
__device__ __forceinline__ ULL add2(ULL a, ULL b) {
    ULL d; asm("add.rn.f32x2 %0, %1, %2;" : "=l"(d) : "l"(a), "l"(b)); return d;
}
__device__ __forceinline__ ULL pk(float lo, float hi) {
    ULL d; asm("mov.b64 %0, {%1, %2};" : "=l"(d) : "f"(lo), "f"(hi)); return d;
}
__device__ __forceinline__ float2 upk(ULL v) {
    float2 r; asm("mov.b64 {%0, %1}, %2;" : "=f"(r.x), "=f"(r.y) : "l"(v)); return r;
}

// ---------- constant memory: Ac matrices (warp-uniform reads -> LDC port) ----
// layout: [0 .. 511]   = pep_Ac (32 x 16)
//         [512 .. 6655] = hla_Ac (384 x 16)
__constant__ float c_Ac[416 * 16];

// ---------- static scratch ----------
__device__ float g_UP[4096 * 256];
__device__ float g_UH[4096 * 256];
__device__ float g_W1cP[256 * 358];
__device__ float g_W1cH[256 * 154];
__device__ float g_H1P[4096 * 358];
__device__ float g_H1H[4096 * 154];
__device__ float2 g_statP[4096 * 6];
__device__ float2 g_statH[4096 * 6];

struct EncArgs { const float* emb; const float* mask; const float* Bc; float* U; };
struct PreArgs { const float* A; const float* B; float* C; int N, K, nbx, nblocks; };
struct GemmArgs { const float* A; const float* B; const float* bias; float* C; int N, K, ldc; };

// =====================================================================
// Encoder core — R2-proven d=2 structure, Ac from __constant__.
// block = 4 warps = 2 samples; warp w: sample w>>1, d-half w&1;
// thread: 2 consecutive d; q-pair packed f32x2 accumulators;
// front-batched 8-row LDG groups (MLP_p1 = 8).
// =====================================================================
template<int L, int OFF>
__device__ __forceinline__ void encoder_core(const EncArgs& e, char* smem)
{
    ULL* mdup = (ULL*)smem;                           // [2][L] dup masks
    // phase-2 overlay
    float* Bcs = (float*)smem;                        // 2048
    float* Vs  = (float*)(smem + 8192);               // 2 * 16 * 130

    const int tid  = threadIdx.x;
    const int w    = tid >> 5;
    const int lane = tid & 31;
    const int b0   = blockIdx.x * 2;
    const int s    = w >> 1;
    const int h    = w & 1;

    for (int i = tid; i < 2 * L; i += 128) {
        int ss = i / L, l = i - ss * L;
        float m = e.mask[(size_t)(b0 + ss) * L + l];
        mdup[i] = pk(m, m);
    }
    __syncthreads();

    const ULL* xg = (const ULL*)(e.emb + (size_t)(b0 + s) * L * 128) + h * 32 + lane;
    const ULL* mp = mdup + s * L;
    const ulonglong2* acp = (const ulonglong2*)(c_Ac + OFF);   // [L][4] in constant

    ULL V[16];
#pragma unroll
    for (int i = 0; i < 16; i++) V[i] = 0ull;

    for (int l0 = 0; l0 < L; l0 += 8) {
        ULL xb[8];
#pragma unroll
        for (int u = 0; u < 8; u++) xb[u] = xg[(size_t)(l0 + u) * 64];
#pragma unroll
        for (int u = 0; u < 8; u++) {
            const int l = l0 + u;
            ULL xm = mul2(xb[u], mp[l]);
            float2 f = upk(xm);
            ULL xl = pk(f.x, f.x);
            ULL xh = pk(f.y, f.y);
            ulonglong2 a01 = acp[l * 4 + 0];
            ulonglong2 a23 = acp[l * 4 + 1];
            ulonglong2 a45 = acp[l * 4 + 2];
            ulonglong2 a67 = acp[l * 4 + 3];
            fma2(V[0],  a01.x, xl);  fma2(V[1],  a01.x, xh);
            fma2(V[2],  a01.y, xl);  fma2(V[3],  a01.y, xh);
            fma2(V[4],  a23.x, xl);  fma2(V[5],  a23.x, xh);
            fma2(V[6],  a23.y, xl);  fma2(V[7],  a23.y, xh);
            fma2(V[8],  a45.x, xl);  fma2(V[9],  a45.x, xh);
            fma2(V[10], a45.y, xl);  fma2(V[11], a45.y, xh);
            fma2(V[12], a67.x, xl);  fma2(V[13], a67.y, xl);
            fma2(V[14], a67.x, xh);  fma2(V[15], a67.y, xh);
        }
    }
    __syncthreads();   // mdup dead

    // stage V: Vs[s][q][d], pitch 130
    const int d0 = h * 64 + lane * 2;
    {
        float* vb = Vs + s * 2080;
#pragma unroll
        for (int qq = 0; qq < 8; qq++) {
            ULL vlo, vhi;
            if (qq < 6)      { vlo = V[2 * qq]; vhi = V[2 * qq + 1]; }
            else if (qq == 6){ vlo = V[12];     vhi = V[14]; }
            else             { vlo = V[13];     vhi = V[15]; }
            float2 v0 = upk(vlo);   // d0
            float2 v1 = upk(vhi);   // d0+1
            vb[(2 * qq)     * 130 + d0]     = v0.x;
            vb[(2 * qq + 1) * 130 + d0]     = v0.y;
            vb[(2 * qq)     * 130 + d0 + 1] = v1.x;
            vb[(2 * qq + 1) * 130 + d0 + 1] = v1.y;
        }
    }
    for (int i = tid; i < 2048; i += 128) Bcs[i] = e.Bc[i];
    __syncthreads();

    // U = V @ Bc : warp covers 8 q x 16 r of its sample
    {
        const int q  = h * 8 + (lane >> 2);
        const int r0 = (lane & 3) * 4;
        ULL u0 = 0ull, u1 = 0ull;
        const float* vrow = Vs + s * 2080 + q * 130;
#pragma unroll 8
        for (int d = 0; d < 128; d++) {
            float v = vrow[d];
            ULL vv = pk(v, v);
            ulonglong2 b2 = *(const ulonglong2*)(Bcs + d * 16 + r0);
            fma2(u0, vv, b2.x);
            fma2(u1, vv, b2.y);
        }
        ULL* dst = (ULL*)(e.U + (size_t)(b0 + s) * 256 + q * 16 + r0);
        dst[0] = u0; dst[1] = u1;
    }
}

// =====================================================================
// Weight precombine path (dynamic smem), 32x32 tiles
// =====================================================================
__device__ __forceinline__ void precombine_path(const PreArgs& p, int bx, char* smem)
{
    float* As = (float*)smem;
    float* Bs = As + 32 * 33;
    const int tid = threadIdx.x;
    const int tx = tid & 15, ty = tid >> 4;
    const int bn = (bx % p.nbx) * 32;
    const int bm = (bx / p.nbx) * 32;
    const int M = 256;

    float c[4][2];
#pragma unroll
    for (int i = 0; i < 4; i++) { c[i][0] = 0.f; c[i][1] = 0.f; }

    for (int k0 = 0; k0 < p.K; k0 += 32) {
#pragma unroll
        for (int i = 0; i < 8; i++) {
            int idx = tid + i * 128;
            int m = idx >> 5, k = idx & 31;
            int kg = k0 + k;
            As[k * 33 + m] = (kg < p.K && (bm + m) < M) ? p.A[(size_t)(bm + m) * p.K + kg] : 0.f;
            int kb = idx >> 5, nb = idx & 31;
            int kgb = k0 + kb, ng = bn + nb;
            Bs[kb * 33 + nb] = (kgb < p.K && ng < p.N) ? p.B[(size_t)kgb * p.N + ng] : 0.f;
        }
        __syncthreads();
#pragma unroll
        for (int kk = 0; kk < 32; kk++) {
            float b0 = Bs[kk * 33 + tx * 2], b1 = Bs[kk * 33 + tx * 2 + 1];
#pragma unroll
            for (int i = 0; i < 4; i++) {
                float a = As[kk * 33 + ty * 4 + i];
                c[i][0] += a * b0;
                c[i][1] += a * b1;
            }
        }
        __syncthreads();
    }
#pragma unroll
    for (int i = 0; i < 4; i++) {
        int m = bm + ty * 4 + i, n = bn + tx * 2;
        if (m < M) {
            if (n < p.N)     p.C[(size_t)m * p.N + n]     = c[i][0];
            if (n + 1 < p.N) p.C[(size_t)m * p.N + n + 1] = c[i][1];
        }
    }
}

// =====================================================================
// Fused prep: z=0 P encoder, z=1 H encoder, z=2 both precombines
// =====================================================================
__global__ __launch_bounds__(128, 5)
void prep_fused(EncArgs e0, EncArgs e1, PreArgs p0, PreArgs p1)
{
    extern __shared__ __align__(16) char smem[];
    const int z = blockIdx.z;
    if (z == 0)      encoder_core<32, 0>(e0, smem);
    else if (z == 1) encoder_core<384, 512>(e1, smem);
    else {
        if ((int)blockIdx.x < p0.nblocks) precombine_path(p0, blockIdx.x, smem);
        else if ((int)blockIdx.x < p0.nblocks + p1.nblocks)
            precombine_path(p1, blockIdx.x - p0.nblocks, smem);
    }
}

// =====================================================================
// GEMM micro-kernel: 64x64 tile, BK=16, 256 threads, 4m x 4n per thread.
// Single-buffered, conflict-free smem, dup via pk on ALU pipe.
// =====================================================================
#define GEMM_DECL()                                                     \
    __shared__ float As[16][68];                                        \
    __shared__ float Bs[16][68];                                        \
    const int tid = threadIdx.x;                                        \
    const int tx  = tid & 15;       /* 4n  */                           \
    const int ty  = tid >> 4;       /* 4m (16 x 4 = 64) */              \
    const int a_k = (tid & 7) * 2;  /* 0..14 */                         \
    const int a_m = tid >> 3;       /* 0..31 */                         \
    const int b_n = tid & 63;                                           \
    const int b_k = tid >> 6;       /* 0..3 */                          \
    float2 pa[2]; float pb[4];                                          \
    ULL c[2][4];                                                        \
    _Pragma("unroll")                                                   \
    for (int i = 0; i < 2; i++)                                         \
        _Pragma("unroll")                                               \
        for (int j = 0; j < 4; j++) c[i][j] = 0ull;

#define GEMM_STORE_SMEM()                                               \
    _Pragma("unroll")                                                   \
    for (int i = 0; i < 2; i++) {                                       \
        int m = a_m + i * 32;                                           \
        As[a_k][m]     = pa[i].x;                                       \
        As[a_k + 1][m] = pa[i].y;                                       \
    }                                                                   \
    _Pragma("unroll")                                                   \
    for (int i = 0; i < 4; i++) Bs[b_k + i * 4][b_n] = pb[i];

#define GEMM_MMA()                                                      \
    _Pragma("unroll")                                                   \
    for (int kk = 0; kk < 16; kk++) {                                   \
        ulonglong2 av = *(const ulonglong2*)&As[kk][ty * 4];            \
        ULL a[2] = {av.x, av.y};                                        \
        float4 bv = *(const float4*)&Bs[kk][tx * 4];                    \
        ULL b[4] = {pk(bv.x, bv.x), pk(bv.y, bv.y),                     \
                    pk(bv.z, bv.z), pk(bv.w, bv.w)};                    \
        _Pragma("unroll")                                               \
        for (int i = 0; i < 2; i++)                                     \
            _Pragma("unroll")                                           \
            for (int j = 0; j < 4; j++)                                 \
                fma2(c[i][j], a[i], b[j]);                              \
    }

#define GEMM_MAINLOOP(Kv)                                               \
    fetch(0);                                                           \
    for (int k0 = 0; k0 < (Kv); k0 += 16) {                             \
        GEMM_STORE_SMEM();                                              \
        __syncthreads();                                                \
        if (k0 + 16 < (Kv)) fetch(k0 + 16);                             \
        GEMM_MMA();                                                     \
        __syncthreads();                                                \
    }

// ---------------------------------------------------------------------
// GEMM1: H1 = U @ W1c + b1, plus per-xtile LN partial stats in epilogue.
// ---------------------------------------------------------------------
__global__ __launch_bounds__(256, 4)
void gemm1_fused(GemmArgs g0, GemmArgs g1)
{
    const GemmArgs g = blockIdx.z ? g1 : g0;
    float2* stat = blockIdx.z ? g_statH : g_statP;
    const int bn = blockIdx.x * 64;
    if (bn >= g.N) return;
    const int bm = blockIdx.y * 64;

    GEMM_DECL();

    auto fetch = [&](int k0) {
        int kg = k0 + a_k;
#pragma unroll
        for (int i = 0; i < 2; i++) {
            int m = bm + a_m + i * 32;
            pa[i] = *(const float2*)(g.A + (size_t)m * g.K + kg);   // K=256 in-bounds
        }
#pragma unroll
        for (int i = 0; i < 4; i++) {
            int kgb = k0 + b_k + i * 4;
            int ng = bn + b_n;
            pb[i] = (ng < g.N) ? g.B[(size_t)kgb * g.N + ng] : 0.f;
        }
    };

    GEMM_MAINLOOP(256);

    // epilogue: bias, write C, per-row (sum, sumsq) partials
    ULL sAcc[2], qAcc[2];
#pragma unroll
    for (int i = 0; i < 2; i++) { sAcc[i] = 0ull; qAcc[i] = 0ull; }

#pragma unroll
    for (int j = 0; j < 4; j++) {
        int n = bn + tx * 4 + j;
        bool ok = (n < g.N);
        float bvs = ok ? g.bias[n] : 0.f;
        ULL bb = pk(bvs, bvs);
#pragma unroll
        for (int i = 0; i < 2; i++) {
            ULL val = ok ? add2(c[i][j], bb) : 0ull;
            if (ok) {
                float2 v = upk(val);
                int m = bm + ty * 4 + 2 * i;
                g.C[(size_t)m * g.ldc + n]       = v.x;
                g.C[(size_t)(m + 1) * g.ldc + n] = v.y;
            }
            sAcc[i] = add2(sAcc[i], val);
            fma2(qAcc[i], val, val);
        }
    }
    // reduce over 16 tx lanes (half-warp shares ty)
#pragma unroll
    for (int i = 0; i < 2; i++) {
        float2 sv = upk(sAcc[i]);
        float2 qv = upk(qAcc[i]);
#pragma unroll
        for (int o = 1; o < 16; o <<= 1) {
            sv.x += __shfl_xor_sync(0xffffffffu, sv.x, o);
            sv.y += __shfl_xor_sync(0xffffffffu, sv.y, o);
            qv.x += __shfl_xor_sync(0xffffffffu, qv.x, o);
            qv.y += __shfl_xor_sync(0xffffffffu, qv.y, o);
        }
        if (tx == 0) {
            int m = bm + ty * 4 + 2 * i;
            stat[(size_t)m * 6 + blockIdx.x]       = make_float2(sv.x, qv.x);
            stat[(size_t)(m + 1) * 6 + blockIdx.x] = make_float2(sv.y, qv.y);
        }
    }
}

// ---------------------------------------------------------------------
// GEMM2: out = relu((H1 - mu)*rstd*gam + bet) @ W2 + b2
// ---------------------------------------------------------------------
__global__ __launch_bounds__(256, 4)
void gemm2_lnA(GemmArgs g0, GemmArgs g1,
               const float* __restrict__ gm0, const float* __restrict__ bt0,
               const float* __restrict__ gm1, const float* __restrict__ bt1)
{
    const GemmArgs g = blockIdx.z ? g1 : g0;
    const float2* stat = blockIdx.z ? g_statH : g_statP;
    const int nx = blockIdx.z ? 3 : 6;
    const float* gam = blockIdx.z ? gm1 : gm0;
    const float* bet = blockIdx.z ? bt1 : bt0;
    const int bn = blockIdx.x * 64;
    if (bn >= g.N) return;
    const int bm = blockIdx.y * 64;

    __shared__ float muS[64], rsS[64];

    GEMM_DECL();

    if (tid < 64) {
        int row = bm + tid;
        float s = 0.f, q = 0.f;
        for (int x = 0; x < nx; x++) {
            float2 p = stat[(size_t)row * 6 + x];
            s += p.x; q += p.y;
        }
        float invN = 1.f / (float)g.K;
        float mu = s * invN;
        float var = q * invN - mu * mu;
        muS[tid] = mu;
        rsS[tid] = rsqrtf(var + 1e-5f);
    }
    __syncthreads();

    auto fetch = [&](int k0) {
        int kg = k0 + a_k;
        bool ok0 = (kg < g.K), ok1 = (kg + 1 < g.K);
        float2 gk = make_float2(0.f, 0.f), bb = make_float2(0.f, 0.f);
        if (ok1)      { gk = *(const float2*)(gam + kg); bb = *(const float2*)(bet + kg); }
        else if (ok0) { gk.x = gam[kg]; bb.x = bet[kg]; }
#pragma unroll
        for (int i = 0; i < 2; i++) {
            int mloc = a_m + i * 32;
            int m = bm + mloc;
            float2 v = make_float2(0.f, 0.f);
            if (ok1)      v = *(const float2*)(g.A + (size_t)m * g.K + kg);
            else if (ok0) v.x = g.A[(size_t)m * g.K + kg];
            float mu = muS[mloc], rs = rsS[mloc];
            float2 r = make_float2(0.f, 0.f);
            if (ok0) r.x = fmaxf(0.f, (v.x - mu) * rs * gk.x + bb.x);
            if (ok1) r.y = fmaxf(0.f, (v.y - mu) * rs * gk.y + bb.y);
            pa[i] = r;
        }
#pragma unroll
        for (int i = 0; i < 4; i++) {
            int kgb = k0 + b_k + i * 4;
            int ng = bn + b_n;
            pb[i] = (kgb < g.K && ng < g.N) ? g.B[(size_t)kgb * g.N + ng] : 0.f;
        }
    };

    GEMM_MAINLOOP(g.K);

#pragma unroll
    for (int j = 0; j < 4; j++) {
        int n = bn + tx * 4 + j;
        if (n >= g.N) continue;
        float bvs = g.bias[n];
#pragma unroll
        for (int i = 0; i < 2; i++) {
            float2 v = upk(c[i][j]);
            int m = bm + ty * 4 + 2 * i;
            g.C[(size_t)m * g.ldc + n]       = v.x + bvs;
            g.C[(size_t)(m + 1) * g.ldc + n] = v.y + bvs;
        }
    }
}

// =====================================================================
// Host launcher
// =====================================================================
extern "C" void kernel_launch(void* const* d_in, const int* in_sizes, int n_in,
                              void* d_out, int out_size)
{
    const float* emb_P  = (const float*)d_in[0];
    const float* mask_P = (const float*)d_in[1];
    const float* emb_H  = (const float*)d_in[2];
    const float* mask_H = (const float*)d_in[3];
    const float* pep_Bc = (const float*)d_in[4];
    const float* pep_Ac = (const float*)d_in[5];
    const float* pep_Hc = (const float*)d_in[6];
    const float* pep_W1 = (const float*)d_in[7];
    const float* pep_b1 = (const float*)d_in[8];
    const float* pep_g  = (const float*)d_in[9];
    const float* pep_be = (const float*)d_in[10];
    const float* pep_W2 = (const float*)d_in[11];
    const float* pep_b2 = (const float*)d_in[12];
    const float* hla_Bc = (const float*)d_in[13];
    const float* hla_Ac = (const float*)d_in[14];
    const float* hla_Hc = (const float*)d_in[15];
    const float* hla_W1 = (const float*)d_in[16];
    const float* hla_b1 = (const float*)d_in[17];
    const float* hla_g  = (const float*)d_in[18];
    const float* hla_be = (const float*)d_in[19];
    const float* hla_W2 = (const float*)d_in[20];
    const float* hla_b2 = (const float*)d_in[21];
    float* out = (float*)d_out;

    float *UP, *UH, *W1cP, *W1cH, *H1P, *H1H;
    cudaGetSymbolAddress((void**)&UP,   g_UP);
    cudaGetSymbolAddress((void**)&UH,   g_UH);
    cudaGetSymbolAddress((void**)&W1cP, g_W1cP);
    cudaGetSymbolAddress((void**)&W1cH, g_W1cH);
    cudaGetSymbolAddress((void**)&H1P,  g_H1P);
    cudaGetSymbolAddress((void**)&H1H,  g_H1H);

    // copy Ac matrices into constant memory (graph-capturable async D2D)
    cudaMemcpyToSymbolAsync(c_Ac, pep_Ac, 32 * 16 * sizeof(float), 0,
                            cudaMemcpyDeviceToDevice, 0);
    cudaMemcpyToSymbolAsync(c_Ac, hla_Ac, 384 * 16 * sizeof(float),
                            512 * sizeof(float), cudaMemcpyDeviceToDevice, 0);

    // dyn smem: phase1 masks (2*384*8 = 6144) ; phase2 = 24832
    const int smemPrep = 24832;
    cudaFuncSetAttribute(prep_fused, cudaFuncAttributeMaxDynamicSharedMemorySize, smemPrep);

    // one launch: both encoders + both precombines (z=2 rides free)
    {
        EncArgs eP { emb_P, mask_P, pep_Bc, UP };
        EncArgs eH { emb_H, mask_H, hla_Bc, UH };
        PreArgs pP { pep_Hc, pep_W1, W1cP, 358, 358, 12, 96 };
        PreArgs pH { hla_Hc, hla_W1, W1cH, 154, 154, 5, 40 };
        prep_fused<<<dim3(2048, 1, 3), 128, smemPrep>>>(eP, eH, pP, pH);
    }

    // GEMM1: H1 = U @ W1c + b1  (+ LN partial stats)
    {
        GemmArgs gp { UP, W1cP, pep_b1, H1P, 358, 256, 358 };
        GemmArgs gh { UH, W1cH, hla_b1, H1H, 154, 256, 154 };
        gemm1_fused<<<dim3(6, 64, 2), 256>>>(gp, gh);
    }

    // GEMM2: out = relu(LN(H1)) @ W2 + b2
    {
        GemmArgs gp { H1P, pep_W2, pep_b2, out,       358, 358, 512 };
        GemmArgs gh { H1H, hla_W2, hla_b2, out + 358, 154, 154, 512 };
        gemm2_lnA<<<dim3(6, 64, 2), 256>>>(gp, gh,
                                           pep_g, pep_be, hla_g, hla_be);
    }
}

// round 10
// speedup vs baseline: 1.0990x; 1.0990x over previous
#include <cuda_runtime.h>
#include <cstdint>

#define ULL unsigned long long

// ---------- packed f32x2 helpers (sm_100+ PTX) ----------
__device__ __forceinline__ void fma2(ULL& d, ULL a, ULL b) {
    asm("fma.rn.f32x2 %0, %1, %2, %0;" : "+l"(d) : "l"(a), "l"(b));
}
__device__ __forceinline__ ULL mul2(ULL a, ULL b) {
    ULL d; asm("mul.rn.f32x2 %0, %1, %2;" : "=l"(d) : "l"(a), "l"(b)); return d;
}
__device__ __forceinline__ ULL add2(ULL a, ULL b) {
    ULL d; asm("add.rn.f32x2 %0, %1, %2;" : "=l"(d) : "l"(a), "l"(b)); return d;
}
__device__ __forceinline__ ULL pk(float lo, float hi) {
    ULL d; asm("mov.b64 %0, {%1, %2};" : "=l"(d) : "f"(lo), "f"(hi)); return d;
}
__device__ __forceinline__ float2 upk(ULL v) {
    float2 r; asm("mov.b64 {%0, %1}, %2;" : "=f"(r.x), "=f"(r.y) : "l"(v)); return r;
}

// ---------- static scratch ----------
__device__ float g_UP[4096 * 256];
__device__ float g_UH[4096 * 256];
__device__ float g_W1cP[256 * 358];
__device__ float g_W1cH[256 * 154];
__device__ float g_H1P[4096 * 358];
__device__ float g_H1H[4096 * 154];
__device__ float2 g_statP[4096 * 6];
__device__ float2 g_statH[4096 * 6];

struct EncArgs { const float* emb; const float* mask; const float* Ac; const float* Bc; float* U; };
struct PreArgs { const float* A; const float* B; float* C; int N, K, nbx, nblocks; };
struct GemmArgs { const float* A; const float* B; const float* bias; float* C; int N, K, ldc; };

// =====================================================================
// Encoder core — R2/R8-proven d=2 structure, smem Ac, BATCHED mask loads.
// block = 4 warps = 2 samples; warp w: sample w>>1, d-half w&1;
// thread: 2 consecutive d; q-pair packed f32x2 accumulators;
// front-batched 8-row LDG groups (MLP_p1 = 8).
// =====================================================================
template<int L>
__device__ __forceinline__ void encoder_core(const EncArgs& e, char* smem)
{
    float* acs   = (float*)smem;                      // L*16 raw Ac
    float* maskS = (float*)(smem + (size_t)L * 64);   // [2][L] raw masks
    // phase-2 overlay
    float* Bcs = (float*)smem;                        // 2048
    float* Vs  = (float*)(smem + 8192);               // 2 * 16 * 130

    const int tid  = threadIdx.x;
    const int w    = tid >> 5;
    const int lane = tid & 31;
    const int b0   = blockIdx.x * 2;
    const int s    = w >> 1;
    const int h    = w & 1;

    for (int i = tid; i < L * 16; i += 128) acs[i] = e.Ac[i];
    for (int i = tid; i < 2 * L; i += 128) {
        int ss = i / L, l = i - ss * L;
        maskS[i] = e.mask[(size_t)(b0 + ss) * L + l];
    }
    __syncthreads();

    const ULL* xg = (const ULL*)(e.emb + (size_t)(b0 + s) * L * 128) + h * 32 + lane;
    const float* msk = maskS + s * L;
    const ulonglong2* acp = (const ulonglong2*)acs;   // [L][4]

    ULL V[16];
#pragma unroll
    for (int i = 0; i < 16; i++) V[i] = 0ull;

    for (int l0 = 0; l0 < L; l0 += 8) {
        ULL xb[8];
#pragma unroll
        for (int u = 0; u < 8; u++) xb[u] = xg[(size_t)(l0 + u) * 64];
        // batched mask loads: 2 uniform LDS.128 per 8 rows
        float4 ma = *(const float4*)(msk + l0);
        float4 mb = *(const float4*)(msk + l0 + 4);
        float mm8[8] = {ma.x, ma.y, ma.z, ma.w, mb.x, mb.y, mb.z, mb.w};
#pragma unroll
        for (int u = 0; u < 8; u++) {
            const int l = l0 + u;
            ULL xm = mul2(xb[u], pk(mm8[u], mm8[u]));
            float2 f = upk(xm);
            ULL xl = pk(f.x, f.x);
            ULL xh = pk(f.y, f.y);
            ulonglong2 a01 = acp[l * 4 + 0];
            ulonglong2 a23 = acp[l * 4 + 1];
            ulonglong2 a45 = acp[l * 4 + 2];
            ulonglong2 a67 = acp[l * 4 + 3];
            fma2(V[0],  a01.x, xl);  fma2(V[1],  a01.x, xh);
            fma2(V[2],  a01.y, xl);  fma2(V[3],  a01.y, xh);
            fma2(V[4],  a23.x, xl);  fma2(V[5],  a23.x, xh);
            fma2(V[6],  a23.y, xl);  fma2(V[7],  a23.y, xh);
            fma2(V[8],  a45.x, xl);  fma2(V[9],  a45.x, xh);
            fma2(V[10], a45.y, xl);  fma2(V[11], a45.y, xh);
            fma2(V[12], a67.x, xl);  fma2(V[13], a67.y, xl);
            fma2(V[14], a67.x, xh);  fma2(V[15], a67.y, xh);
        }
    }
    __syncthreads();   // acs/maskS dead

    // stage V: Vs[s][q][d], pitch 130
    const int d0 = h * 64 + lane * 2;
    {
        float* vb = Vs + s * 2080;
#pragma unroll
        for (int qq = 0; qq < 8; qq++) {
            ULL vlo, vhi;
            if (qq < 6)      { vlo = V[2 * qq]; vhi = V[2 * qq + 1]; }
            else if (qq == 6){ vlo = V[12];     vhi = V[14]; }
            else             { vlo = V[13];     vhi = V[15]; }
            float2 v0 = upk(vlo);   // d0
            float2 v1 = upk(vhi);   // d0+1
            vb[(2 * qq)     * 130 + d0]     = v0.x;
            vb[(2 * qq + 1) * 130 + d0]     = v0.y;
            vb[(2 * qq)     * 130 + d0 + 1] = v1.x;
            vb[(2 * qq + 1) * 130 + d0 + 1] = v1.y;
        }
    }
    for (int i = tid; i < 2048; i += 128) Bcs[i] = e.Bc[i];
    __syncthreads();

    // U = V @ Bc : warp covers 8 q x 16 r of its sample
    {
        const int q  = h * 8 + (lane >> 2);
        const int r0 = (lane & 3) * 4;
        ULL u0 = 0ull, u1 = 0ull;
        const float* vrow = Vs + s * 2080 + q * 130;
#pragma unroll 8
        for (int d = 0; d < 128; d++) {
            float v = vrow[d];
            ULL vv = pk(v, v);
            ulonglong2 b2 = *(const ulonglong2*)(Bcs + d * 16 + r0);
            fma2(u0, vv, b2.x);
            fma2(u1, vv, b2.y);
        }
        ULL* dst = (ULL*)(e.U + (size_t)(b0 + s) * 256 + q * 16 + r0);
        dst[0] = u0; dst[1] = u1;
    }
}

// =====================================================================
// Weight precombine path (dynamic smem), 32x32 tiles
// =====================================================================
__device__ __forceinline__ void precombine_path(const PreArgs& p, int bx, char* smem)
{
    float* As = (float*)smem;
    float* Bs = As + 32 * 33;
    const int tid = threadIdx.x;
    const int tx = tid & 15, ty = tid >> 4;
    const int bn = (bx % p.nbx) * 32;
    const int bm = (bx / p.nbx) * 32;
    const int M = 256;

    float c[4][2];
#pragma unroll
    for (int i = 0; i < 4; i++) { c[i][0] = 0.f; c[i][1] = 0.f; }

    for (int k0 = 0; k0 < p.K; k0 += 32) {
#pragma unroll
        for (int i = 0; i < 8; i++) {
            int idx = tid + i * 128;
            int m = idx >> 5, k = idx & 31;
            int kg = k0 + k;
            As[k * 33 + m] = (kg < p.K && (bm + m) < M) ? p.A[(size_t)(bm + m) * p.K + kg] : 0.f;
            int kb = idx >> 5, nb = idx & 31;
            int kgb = k0 + kb, ng = bn + nb;
            Bs[kb * 33 + nb] = (kgb < p.K && ng < p.N) ? p.B[(size_t)kgb * p.N + ng] : 0.f;
        }
        __syncthreads();
#pragma unroll
        for (int kk = 0; kk < 32; kk++) {
            float b0 = Bs[kk * 33 + tx * 2], b1 = Bs[kk * 33 + tx * 2 + 1];
#pragma unroll
            for (int i = 0; i < 4; i++) {
                float a = As[kk * 33 + ty * 4 + i];
                c[i][0] += a * b0;
                c[i][1] += a * b1;
            }
        }
        __syncthreads();
    }
#pragma unroll
    for (int i = 0; i < 4; i++) {
        int m = bm + ty * 4 + i, n = bn + tx * 2;
        if (m < M) {
            if (n < p.N)     p.C[(size_t)m * p.N + n]     = c[i][0];
            if (n + 1 < p.N) p.C[(size_t)m * p.N + n + 1] = c[i][1];
        }
    }
}

// =====================================================================
// Fused prep: z=0 P encoder, z=1 H encoder, z=2 both precombines
// =====================================================================
__global__ __launch_bounds__(128, 5)
void prep_fused(EncArgs e0, EncArgs e1, PreArgs p0, PreArgs p1)
{
    extern __shared__ __align__(16) char smem[];
    const int z = blockIdx.z;
    if (z == 0)      encoder_core<32>(e0, smem);
    else if (z == 1) encoder_core<384>(e1, smem);
    else {
        if ((int)blockIdx.x < p0.nblocks) precombine_path(p0, blockIdx.x, smem);
        else if ((int)blockIdx.x < p0.nblocks + p1.nblocks)
            precombine_path(p1, blockIdx.x - p0.nblocks, smem);
    }
}

// =====================================================================
// GEMM micro-kernel: 64x64 tile, BK=32, 256 threads, 4m x 4n per thread.
// Single-buffered, conflict-free smem, dup via pk on ALU pipe.
// =====================================================================
#define GEMM_DECL()                                                     \
    __shared__ float As[32][68];                                        \
    __shared__ float Bs[32][68];                                        \
    const int tid = threadIdx.x;                                        \
    const int tx  = tid & 15;       /* 4n  */                           \
    const int ty  = tid >> 4;       /* 4m (16 x 4 = 64) */              \
    const int a_k = (tid & 15) * 2; /* 0..30 */                         \
    const int a_m = tid >> 4;       /* 0..15 */                         \
    const int b_n = tid & 63;                                           \
    const int b_k = tid >> 6;       /* 0..3 */                          \
    float2 pa[4]; float pb[8];                                          \
    ULL c[2][4];                                                        \
    _Pragma("unroll")                                                   \
    for (int i = 0; i < 2; i++)                                         \
        _Pragma("unroll")                                               \
        for (int j = 0; j < 4; j++) c[i][j] = 0ull;

#define GEMM_STORE_SMEM()                                               \
    _Pragma("unroll")                                                   \
    for (int i = 0; i < 4; i++) {                                       \
        int m = a_m + i * 16;                                           \
        As[a_k][m]     = pa[i].x;                                       \
        As[a_k + 1][m] = pa[i].y;                                       \
    }                                                                   \
    _Pragma("unroll")                                                   \
    for (int i = 0; i < 8; i++) Bs[b_k + i * 4][b_n] = pb[i];

#define GEMM_MMA()                                                      \
    _Pragma("unroll")                                                   \
    for (int kk = 0; kk < 32; kk++) {                                   \
        ulonglong2 av = *(const ulonglong2*)&As[kk][ty * 4];            \
        ULL a[2] = {av.x, av.y};                                        \
        float4 bv = *(const float4*)&Bs[kk][tx * 4];                    \
        ULL b[4] = {pk(bv.x, bv.x), pk(bv.y, bv.y),                     \
                    pk(bv.z, bv.z), pk(bv.w, bv.w)};                    \
        _Pragma("unroll")                                               \
        for (int i = 0; i < 2; i++)                                     \
            _Pragma("unroll")                                           \
            for (int j = 0; j < 4; j++)                                 \
                fma2(c[i][j], a[i], b[j]);                              \
    }

#define GEMM_MAINLOOP(Kv)                                               \
    fetch(0);                                                           \
    for (int k0 = 0; k0 < (Kv); k0 += 32) {                             \
        GEMM_STORE_SMEM();                                              \
        __syncthreads();                                                \
        if (k0 + 32 < (Kv)) fetch(k0 + 32);                             \
        GEMM_MMA();                                                     \
        __syncthreads();                                                \
    }

// ---------------------------------------------------------------------
// GEMM1: H1 = U @ W1c + b1, plus per-xtile LN partial stats in epilogue.
// ---------------------------------------------------------------------
__global__ __launch_bounds__(256, 4)
void gemm1_fused(GemmArgs g0, GemmArgs g1)
{
    const GemmArgs g = blockIdx.z ? g1 : g0;
    float2* stat = blockIdx.z ? g_statH : g_statP;
    const int bn = blockIdx.x * 64;
    if (bn >= g.N) return;
    const int bm = blockIdx.y * 64;

    GEMM_DECL();

    auto fetch = [&](int k0) {
        int kg = k0 + a_k;
#pragma unroll
        for (int i = 0; i < 4; i++) {
            int m = bm + a_m + i * 16;
            pa[i] = *(const float2*)(g.A + (size_t)m * g.K + kg);   // K=256 in-bounds
        }
#pragma unroll
        for (int i = 0; i < 8; i++) {
            int kgb = k0 + b_k + i * 4;
            int ng = bn + b_n;
            pb[i] = (ng < g.N) ? g.B[(size_t)kgb * g.N + ng] : 0.f;
        }
    };

    GEMM_MAINLOOP(256);

    // epilogue: bias, write C, per-row (sum, sumsq) partials
    ULL sAcc[2], qAcc[2];
#pragma unroll
    for (int i = 0; i < 2; i++) { sAcc[i] = 0ull; qAcc[i] = 0ull; }

#pragma unroll
    for (int j = 0; j < 4; j++) {
        int n = bn + tx * 4 + j;
        bool ok = (n < g.N);
        float bvs = ok ? g.bias[n] : 0.f;
        ULL bb = pk(bvs, bvs);
#pragma unroll
        for (int i = 0; i < 2; i++) {
            ULL val = ok ? add2(c[i][j], bb) : 0ull;
            if (ok) {
                float2 v = upk(val);
                int m = bm + ty * 4 + 2 * i;
                g.C[(size_t)m * g.ldc + n]       = v.x;
                g.C[(size_t)(m + 1) * g.ldc + n] = v.y;
            }
            sAcc[i] = add2(sAcc[i], val);
            fma2(qAcc[i], val, val);
        }
    }
    // reduce over 16 tx lanes (half-warp shares ty)
#pragma unroll
    for (int i = 0; i < 2; i++) {
        float2 sv = upk(sAcc[i]);
        float2 qv = upk(qAcc[i]);
#pragma unroll
        for (int o = 1; o < 16; o <<= 1) {
            sv.x += __shfl_xor_sync(0xffffffffu, sv.x, o);
            sv.y += __shfl_xor_sync(0xffffffffu, sv.y, o);
            qv.x += __shfl_xor_sync(0xffffffffu, qv.x, o);
            qv.y += __shfl_xor_sync(0xffffffffu, qv.y, o);
        }
        if (tx == 0) {
            int m = bm + ty * 4 + 2 * i;
            stat[(size_t)m * 6 + blockIdx.x]       = make_float2(sv.x, qv.x);
            stat[(size_t)(m + 1) * 6 + blockIdx.x] = make_float2(sv.y, qv.y);
        }
    }
}

// ---------------------------------------------------------------------
// GEMM2: out = relu((H1 - mu)*rstd*gam + bet) @ W2 + b2
// ---------------------------------------------------------------------
__global__ __launch_bounds__(256, 4)
void gemm2_lnA(GemmArgs g0, GemmArgs g1,
               const float* __restrict__ gm0, const float* __restrict__ bt0,
               const float* __restrict__ gm1, const float* __restrict__ bt1)
{
    const GemmArgs g = blockIdx.z ? g1 : g0;
    const float2* stat = blockIdx.z ? g_statH : g_statP;
    const int nx = blockIdx.z ? 3 : 6;
    const float* gam = blockIdx.z ? gm1 : gm0;
    const float* bet = blockIdx.z ? bt1 : bt0;
    const int bn = blockIdx.x * 64;
    if (bn >= g.N) return;
    const int bm = blockIdx.y * 64;

    __shared__ float muS[64], rsS[64];

    GEMM_DECL();

    if (tid < 64) {
        int row = bm + tid;
        float s = 0.f, q = 0.f;
        for (int x = 0; x < nx; x++) {
            float2 p = stat[(size_t)row * 6 + x];
            s += p.x; q += p.y;
        }
        float invN = 1.f / (float)g.K;
        float mu = s * invN;
        float var = q * invN - mu * mu;
        muS[tid] = mu;
        rsS[tid] = rsqrtf(var + 1e-5f);
    }
    __syncthreads();

    auto fetch = [&](int k0) {
        int kg = k0 + a_k;
        bool ok0 = (kg < g.K), ok1 = (kg + 1 < g.K);
        float2 gk = make_float2(0.f, 0.f), bb = make_float2(0.f, 0.f);
        if (ok1)      { gk = *(const float2*)(gam + kg); bb = *(const float2*)(bet + kg); }
        else if (ok0) { gk.x = gam[kg]; bb.x = bet[kg]; }
#pragma unroll
        for (int i = 0; i < 4; i++) {
            int mloc = a_m + i * 16;
            int m = bm + mloc;
            float2 v = make_float2(0.f, 0.f);
            if (ok1)      v = *(const float2*)(g.A + (size_t)m * g.K + kg);
            else if (ok0) v.x = g.A[(size_t)m * g.K + kg];
            float mu = muS[mloc], rs = rsS[mloc];
            float2 r = make_float2(0.f, 0.f);
            if (ok0) r.x = fmaxf(0.f, (v.x - mu) * rs * gk.x + bb.x);
            if (ok1) r.y = fmaxf(0.f, (v.y - mu) * rs * gk.y + bb.y);
            pa[i] = r;
        }
#pragma unroll
        for (int i = 0; i < 8; i++) {
            int kgb = k0 + b_k + i * 4;
            int ng = bn + b_n;
            pb[i] = (kgb < g.K && ng < g.N) ? g.B[(size_t)kgb * g.N + ng] : 0.f;
        }
    };

    GEMM_MAINLOOP(g.K);

#pragma unroll
    for (int j = 0; j < 4; j++) {
        int n = bn + tx * 4 + j;
        if (n >= g.N) continue;
        float bvs = g.bias[n];
#pragma unroll
        for (int i = 0; i < 2; i++) {
            float2 v = upk(c[i][j]);
            int m = bm + ty * 4 + 2 * i;
            g.C[(size_t)m * g.ldc + n]       = v.x + bvs;
            g.C[(size_t)(m + 1) * g.ldc + n] = v.y + bvs;
        }
    }
}

// =====================================================================
// Host launcher
// =====================================================================
extern "C" void kernel_launch(void* const* d_in, const int* in_sizes, int n_in,
                              void* d_out, int out_size)
{
    const float* emb_P  = (const float*)d_in[0];
    const float* mask_P = (const float*)d_in[1];
    const float* emb_H  = (const float*)d_in[2];
    const float* mask_H = (const float*)d_in[3];
    const float* pep_Bc = (const float*)d_in[4];
    const float* pep_Ac = (const float*)d_in[5];
    const float* pep_Hc = (const float*)d_in[6];
    const float* pep_W1 = (const float*)d_in[7];
    const float* pep_b1 = (const float*)d_in[8];
    const float* pep_g  = (const float*)d_in[9];
    const float* pep_be = (const float*)d_in[10];
    const float* pep_W2 = (const float*)d_in[11];
    const float* pep_b2 = (const float*)d_in[12];
    const float* hla_Bc = (const float*)d_in[13];
    const float* hla_Ac = (const float*)d_in[14];
    const float* hla_Hc = (const float*)d_in[15];
    const float* hla_W1 = (const float*)d_in[16];
    const float* hla_b1 = (const float*)d_in[17];
    const float* hla_g  = (const float*)d_in[18];
    const float* hla_be = (const float*)d_in[19];
    const float* hla_W2 = (const float*)d_in[20];
    const float* hla_b2 = (const float*)d_in[21];
    float* out = (float*)d_out;

    float *UP, *UH, *W1cP, *W1cH, *H1P, *H1H;
    cudaGetSymbolAddress((void**)&UP,   g_UP);
    cudaGetSymbolAddress((void**)&UH,   g_UH);
    cudaGetSymbolAddress((void**)&W1cP, g_W1cP);
    cudaGetSymbolAddress((void**)&W1cH, g_W1cH);
    cudaGetSymbolAddress((void**)&H1P,  g_H1P);
    cudaGetSymbolAddress((void**)&H1H,  g_H1H);

    // dyn smem: phase1 (L=384): 384*64 + 2*384*4 = 27648 ; phase2 = 24832
    const int smemPrep = 384 * 64 + 2 * 384 * 4;
    cudaFuncSetAttribute(prep_fused, cudaFuncAttributeMaxDynamicSharedMemorySize, smemPrep);

    // one launch: both encoders + both precombines (z=2 rides free)
    {
        EncArgs eP { emb_P, mask_P, pep_Ac, pep_Bc, UP };
        EncArgs eH { emb_H, mask_H, hla_Ac, hla_Bc, UH };
        PreArgs pP { pep_Hc, pep_W1, W1cP, 358, 358, 12, 96 };
        PreArgs pH { hla_Hc, hla_W1, W1cH, 154, 154, 5, 40 };
        prep_fused<<<dim3(2048, 1, 3), 128, smemPrep>>>(eP, eH, pP, pH);
    }

    // GEMM1: H1 = U @ W1c + b1  (+ LN partial stats)
    {
        GemmArgs gp { UP, W1cP, pep_b1, H1P, 358, 256, 358 };
        GemmArgs gh { UH, W1cH, hla_b1, H1H, 154, 256, 154 };
        gemm1_fused<<<dim3(6, 64, 2), 256>>>(gp, gh);
    }

    // GEMM2: out = relu(LN(H1)) @ W2 + b2
    {
        GemmArgs gp { H1P, pep_W2, pep_b2, out,       358, 358, 512 };
        GemmArgs gh { H1H, hla_W2, hla_b2, out + 358, 154, 154, 512 };
        gemm2_lnA<<<dim3(6, 64, 2), 256>>>(gp, gh,
                                           pep_g, pep_be, hla_g, hla_be);
    }
}